// round 3
// baseline (speedup 1.0000x reference)
#include <cuda_runtime.h>
#include <cuda_bf16.h>
#include <math.h>

// ---------------- problem constants ----------------
#define NN      20000          // nodes
#define NE      320000         // edges
#define RR      10             // runs
#define CC      64             // feature/hidden dim
#define RC      (RR*CC)        // 640 floats per node-row
#define ROWS    (NN*RR)        // 200000 GEMM rows
#define NG      128            // graphs
#define NCLS    10
#define NLAY    4
#define BN_EPS  1e-5f

// ---------------- scratch (device globals; no allocation allowed) ----------------
__device__ float g_H[NN * RC];     // 51.2 MB  post-BN activations, layout [n][r][c]
__device__ float g_Z[NN * RC];     // 51.2 MB  agg output / T2
__device__ float g_T[NN * RC];     // 51.2 MB  T1
__device__ int   g_deg[NN];
__device__ int   g_rowstart[NN + 1];
__device__ int   g_cursor[NN];
__device__ int   g_csr[NE];
__device__ double g_sum[CC];
__device__ double g_sumsq[CC];
__device__ float  g_affA[CC];
__device__ float  g_affC[CC];
__device__ float  g_pooled[(NLAY + 1) * NG * CC];
__device__ int    g_mask_fmt;      // 0 = u8 bool, 1 = int32, 2 = float32

// ---------------- small utility kernels ----------------
__global__ void k_zero_deg() {
    int i = blockIdx.x * blockDim.x + threadIdx.x;
    if (i < NN) g_deg[i] = 0;
}
__global__ void k_zero_pooled() {
    int i = blockIdx.x * blockDim.x + threadIdx.x;
    if (i < (NLAY + 1) * NG * CC) g_pooled[i] = 0.f;
}
__global__ void k_zero_stats() {
    int t = threadIdx.x;
    g_sum[t] = 0.0; g_sumsq[t] = 0.0;
}

// sniff drop_mask dtype encoding from its first 4096 bytes
__global__ void k_detect(const unsigned char* __restrict__ dm) {
    if (threadIdx.x || blockIdx.x) return;
    const unsigned int* w = (const unsigned int*)dm;
    bool i32 = true, f32 = true;
    for (int i = 0; i < 1024; i++) {
        unsigned int v = w[i];
        if (v > 1u) i32 = false;
        if (v != 0u && v != 0x3F800000u) f32 = false;
    }
    g_mask_fmt = i32 ? 1 : (f32 ? 2 : 0);
}

// ---------------- CSR build (keyed by dst) ----------------
__global__ void k_count(const int* __restrict__ ei) {
    int e = blockIdx.x * blockDim.x + threadIdx.x;
    if (e < NE) atomicAdd(&g_deg[ei[NE + e]], 1);
}

__global__ void k_scan() {   // exclusive prefix over g_deg -> g_rowstart/g_cursor
    __shared__ int sm[1024];
    const int ITEMS = 20;    // 1024*20 = 20480 >= NN
    int t = threadIdx.x;
    int base = t * ITEMS;
    int loc[ITEMS];
    int run = 0;
#pragma unroll
    for (int j = 0; j < ITEMS; j++) {
        int i = base + j;
        int v = (i < NN) ? g_deg[i] : 0;
        loc[j] = run; run += v;
    }
    sm[t] = run;
    __syncthreads();
    for (int off = 1; off < 1024; off <<= 1) {
        int v = (t >= off) ? sm[t - off] : 0;
        __syncthreads();
        sm[t] += v;
        __syncthreads();
    }
    int excl = sm[t] - run;
#pragma unroll
    for (int j = 0; j < ITEMS; j++) {
        int i = base + j;
        if (i < NN) { int v = excl + loc[j]; g_rowstart[i] = v; g_cursor[i] = v; }
    }
    if (t == 1023) g_rowstart[NN] = sm[1023];
}

__global__ void k_fill(const int* __restrict__ ei) {
    int e = blockIdx.x * blockDim.x + threadIdx.x;
    if (e < NE) {
        int d = ei[NE + e];
        int pos = atomicAdd(&g_cursor[d], 1);
        g_csr[pos] = ei[e];
    }
}

// ---------------- init: H[n][r][c] = drop ? 0 : x[n][c] ----------------
__global__ void k_init(const float* __restrict__ x, const unsigned char* __restrict__ dm) {
    int i = blockIdx.x * blockDim.x + threadIdx.x;   // float4 index
    if (i >= NN * (RC / 4)) return;
    int n   = i / (RC / 4);
    int rem = i - n * (RC / 4);       // 0..159
    int r   = rem >> 4;               // 16 float4 per run
    int c4  = rem & 15;
    int mi  = r * NN + n;
    int fmt = g_mask_fmt;
    bool drop;
    if (fmt == 0)      drop = dm[mi] != 0;
    else if (fmt == 1) drop = ((const int*)dm)[mi] != 0;
    else               drop = ((const float*)dm)[mi] != 0.f;
    float4 v = make_float4(0.f, 0.f, 0.f, 0.f);
    if (!drop) v = ((const float4*)x)[n * 16 + c4];
    ((float4*)g_H)[i] = v;
}

// ---------------- aggregation: Z[n] = H[n] + sum_{src->n} H[src] ----------------
__global__ void k_agg() {
    int warp = (blockIdx.x * blockDim.x + threadIdx.x) >> 5;
    int lane = threadIdx.x & 31;
    if (warp >= NN) return;
    const float4* __restrict__ Hv = (const float4*)g_H;
    float4* __restrict__ Zv = (float4*)g_Z;
    int s = g_rowstart[warp], e = g_rowstart[warp + 1];
    int selfb = warp * 160 + lane;
    float4 acc[5];
#pragma unroll
    for (int k = 0; k < 5; k++) acc[k] = Hv[selfb + k * 32];
    for (int idx = s; idx < e; idx++) {
        int src = g_csr[idx];
        int b = src * 160 + lane;
#pragma unroll
        for (int k = 0; k < 5; k++) {
            float4 v = Hv[b + k * 32];
            acc[k].x += v.x; acc[k].y += v.y; acc[k].z += v.z; acc[k].w += v.w;
        }
    }
#pragma unroll
    for (int k = 0; k < 5; k++) Zv[selfb + k * 32] = acc[k];
}

// ---------------- GEMM: Y = act(X) @ W + b, fused column sum/sumsq -------------
// APPLY=false: X = g_Z (raw), Y = g_T
// APPLY=true : X = g_T, act = relu(x*A+C) (BN1), Y = g_Z
template <bool APPLY>
__global__ void __launch_bounds__(256) k_gemm(const float* __restrict__ Wg,
                                              const float* __restrict__ bg) {
    __shared__ float2 sW[64][32];
    __shared__ float  sb[64], sA[64], sC[64];
    __shared__ float  redS[8][64], redQ[8][64];
    const float* __restrict__ X = APPLY ? g_T : g_Z;
    float* __restrict__ Y       = APPLY ? g_Z : g_T;
    int tid = threadIdx.x;
    for (int idx = tid; idx < 4096; idx += 256) {
        int k = idx >> 6, j = idx & 63;
        float v = Wg[idx];
        if (j < 32) sW[k][j].x = v; else sW[k][j - 32].y = v;
    }
    if (tid < 64) {
        sb[tid] = bg[tid];
        if (APPLY) { sA[tid] = g_affA[tid]; sC[tid] = g_affC[tid]; }
    }
    __syncthreads();
    int lane = tid & 31, w = tid >> 5;
    float s0 = 0.f, s1 = 0.f, q0 = 0.f, q1 = 0.f;
    int stride = gridDim.x * 8;
    for (int row = blockIdx.x * 8 + w; row < ROWS; row += stride) {
        float z0 = X[row * 64 + lane];
        float z1 = X[row * 64 + 32 + lane];
        if (APPLY) {
            z0 = fmaxf(fmaf(z0, sA[lane],      sC[lane]),      0.f);
            z1 = fmaxf(fmaf(z1, sA[lane + 32], sC[lane + 32]), 0.f);
        }
        float a0 = sb[lane], a1 = sb[lane + 32];
#pragma unroll
        for (int k = 0; k < 32; k++) {
            float zk = __shfl_sync(0xffffffffu, z0, k);
            float2 wv = sW[k][lane];
            a0 = fmaf(zk, wv.x, a0); a1 = fmaf(zk, wv.y, a1);
        }
#pragma unroll
        for (int k = 0; k < 32; k++) {
            float zk = __shfl_sync(0xffffffffu, z1, k);
            float2 wv = sW[k + 32][lane];
            a0 = fmaf(zk, wv.x, a0); a1 = fmaf(zk, wv.y, a1);
        }
        Y[row * 64 + lane]      = a0;
        Y[row * 64 + 32 + lane] = a1;
        s0 += a0; q0 += a0 * a0; s1 += a1; q1 += a1 * a1;
    }
    redS[w][lane] = s0; redS[w][lane + 32] = s1;
    redQ[w][lane] = q0; redQ[w][lane + 32] = q1;
    __syncthreads();
    if (tid < 64) {
        float ts = 0.f, tq = 0.f;
#pragma unroll
        for (int i = 0; i < 8; i++) { ts += redS[i][tid]; tq += redQ[i][tid]; }
        atomicAdd(&g_sum[tid],   (double)ts);
        atomicAdd(&g_sumsq[tid], (double)tq);
    }
}

// ---------------- BN stats -> per-column affine ----------------
__global__ void k_stats(const float* __restrict__ g, const float* __restrict__ b) {
    int t = threadIdx.x;
    double mu  = g_sum[t]   / (double)ROWS;
    double var = g_sumsq[t] / (double)ROWS - mu * mu;
    float A = g[t] * rsqrtf((float)var + BN_EPS);
    g_affA[t] = A;
    g_affC[t] = b[t] - (float)mu * A;
}

// ---------------- normalize (BN2+relu) -> H, plus per-level pooling ----------------
// NORM=false: src = g_H, no write (level 0 pooling only)
// NORM=true : src = g_Z (T2 raw), write H = relu(T2*A+C)
template <bool NORM>
__global__ void k_norm_pool(const int* __restrict__ batch, int lvl) {
    int warp = (blockIdx.x * blockDim.x + threadIdx.x) >> 5;
    int lane = threadIdx.x & 31;
    if (warp >= NN) return;
    const float2* __restrict__ S = (const float2*)(NORM ? g_Z : g_H);
    float2* __restrict__ Hd = (float2*)g_H;
    float A0 = 0.f, A1 = 0.f, C0 = 0.f, C1 = 0.f;
    if (NORM) {
        A0 = g_affA[2 * lane];     A1 = g_affA[2 * lane + 1];
        C0 = g_affC[2 * lane];     C1 = g_affC[2 * lane + 1];
    }
    float mx = 0.f, my = 0.f;
    int base = warp * 320 + lane;   // float2 units: row = 320 float2
#pragma unroll
    for (int r = 0; r < RR; r++) {
        float2 v = S[base + r * 32];
        if (NORM) {
            v.x = fmaxf(fmaf(v.x, A0, C0), 0.f);
            v.y = fmaxf(fmaf(v.y, A1, C1), 0.f);
            Hd[base + r * 32] = v;
        }
        mx += v.x; my += v.y;
    }
    int gidx = batch[warp];
    float* p = &g_pooled[lvl * (NG * CC) + gidx * CC + 2 * lane];
    atomicAdd(p,     mx * 0.1f);
    atomicAdd(p + 1, my * 0.1f);
}

// ---------------- final: sum_l pooled[l] @ fc_w[l] + fc_b[l], log_softmax ------
__global__ void k_final(const float* __restrict__ fcw, const float* __restrict__ fcb,
                        float* __restrict__ out) {
    int g = blockIdx.x;
    int lane = threadIdx.x;
    float acc = -1e30f;
    if (lane < NCLS) {
        acc = 0.f;
#pragma unroll
        for (int l = 0; l < NLAY + 1; l++) {
            acc += fcb[l * NCLS + lane];
            const float* p = &g_pooled[l * (NG * CC) + g * CC];
            const float* w = &fcw[l * (CC * NCLS) + lane];
            for (int c = 0; c < CC; c++) acc = fmaf(p[c], w[c * NCLS], acc);
        }
    }
    float mx = acc;
#pragma unroll
    for (int j = 0; j < NCLS; j++) mx = fmaxf(mx, __shfl_sync(0xffffffffu, acc, j));
    float se = 0.f;
#pragma unroll
    for (int j = 0; j < NCLS; j++) se += expf(__shfl_sync(0xffffffffu, acc, j) - mx);
    if (lane < NCLS) out[g * NCLS + lane] = acc - mx - logf(se);
}

// ---------------- launch ----------------
extern "C" void kernel_launch(void* const* d_in, const int* in_sizes, int n_in,
                              void* d_out, int out_size) {
    const float* x   = (const float*)d_in[0];
    const int*   ei  = (const int*)d_in[1];
    const int*   bat = (const int*)d_in[2];
    const unsigned char* dm = (const unsigned char*)d_in[3];
    const float* cw1 = (const float*)d_in[4];
    const float* cb1 = (const float*)d_in[5];
    const float* bg1 = (const float*)d_in[6];
    const float* bb1 = (const float*)d_in[7];
    const float* cw2 = (const float*)d_in[8];
    const float* cb2 = (const float*)d_in[9];
    const float* bng = (const float*)d_in[10];
    const float* bnb = (const float*)d_in[11];
    const float* fcw = (const float*)d_in[12];
    const float* fcb = (const float*)d_in[13];
    float* out = (float*)d_out;

    // CSR build (dst-keyed)
    k_zero_deg<<<(NN + 255) / 256, 256>>>();
    k_count<<<(NE + 255) / 256, 256>>>(ei);
    k_scan<<<1, 1024>>>();
    k_fill<<<(NE + 255) / 256, 256>>>(ei);

    // init H with node-drop
    k_detect<<<1, 32>>>(dm);
    k_init<<<(NN * (RC / 4) + 255) / 256, 256>>>(x, dm);

    k_zero_pooled<<<((NLAY + 1) * NG * CC + 255) / 256, 256>>>();
    k_norm_pool<false><<<(NN * 32 + 255) / 256, 256>>>(bat, 0);   // level 0 pooling

    for (int i = 0; i < NLAY; i++) {
        k_agg<<<(NN * 32 + 255) / 256, 256>>>();
        k_zero_stats<<<1, 64>>>();
        k_gemm<false><<<1184, 256>>>(cw1 + i * 4096, cb1 + i * 64);
        k_stats<<<1, 64>>>(bg1 + i * 64, bb1 + i * 64);
        k_zero_stats<<<1, 64>>>();
        k_gemm<true><<<1184, 256>>>(cw2 + i * 4096, cb2 + i * 64);
        k_stats<<<1, 64>>>(bng + i * 64, bnb + i * 64);
        k_norm_pool<true><<<(NN * 32 + 255) / 256, 256>>>(bat, i + 1);
    }

    k_final<<<NG, 32>>>(fcw, fcb, out);
}

// round 16
// speedup vs baseline: 1.3910x; 1.3910x over previous
#include <cuda_runtime.h>
#include <cuda_bf16.h>
#include <math.h>

// ---------------- problem constants ----------------
#define NN      20000          // nodes
#define NE      320000         // edges
#define RR      10             // runs
#define CC      64             // feature/hidden dim
#define RC      (RR*CC)        // 640 floats per node-row
#define ROWS    (NN*RR)        // 200000 GEMM rows
#define NBT     (ROWS/64)      // 3125 blocks-tiles of 64 rows
#define NG      128            // graphs
#define NCLS    10
#define NLAY    4
#define NSTAT   (2*NLAY)       // 8 stat slots
#define BN_EPS  1e-5f

// ---------------- scratch (device globals; no allocation allowed) ----------------
__device__ float g_H[NN * RC];     // 51.2 MB  post-BN activations, layout [n][r][c]
__device__ float g_Z[NN * RC];     // 51.2 MB  agg output / T2
__device__ float g_T[NN * RC];     // 51.2 MB  T1
__device__ int   g_deg[NN];
__device__ int   g_rowstart[NN + 1];
__device__ int   g_cursor[NN];
__device__ int   g_csr[NE];
__device__ double g_sum[NSTAT][CC];
__device__ double g_sumsq[NSTAT][CC];
__device__ float  g_affA[CC];
__device__ float  g_affC[CC];
__device__ float  g_pooled[(NLAY + 1) * NG * CC];
__device__ int    g_mask_fmt;      // 0 = u8 bool, 1 = int32, 2 = float32

// ---------------- small utility kernels ----------------
__global__ void k_zero_deg() {
    int i = blockIdx.x * blockDim.x + threadIdx.x;
    if (i < NN) g_deg[i] = 0;
}
// zero pooled buffer + all stat slots (one launch)
__global__ void k_zero_misc() {
    int i = blockIdx.x * blockDim.x + threadIdx.x;
    if (i < (NLAY + 1) * NG * CC) g_pooled[i] = 0.f;
    if (i < NSTAT * CC) {
        ((double*)g_sum)[i] = 0.0;
        ((double*)g_sumsq)[i] = 0.0;
    }
}

// sniff drop_mask dtype encoding from its first 4096 bytes (one warp)
__global__ void k_detect(const unsigned char* __restrict__ dm) {
    int l = threadIdx.x;
    const unsigned int* w = (const unsigned int*)dm;
    bool i32 = true, f32 = true;
    for (int i = l; i < 1024; i += 32) {
        unsigned int v = w[i];
        if (v > 1u) i32 = false;
        if (v != 0u && v != 0x3F800000u) f32 = false;
    }
    i32 = __all_sync(0xffffffffu, i32);
    f32 = __all_sync(0xffffffffu, f32);
    if (l == 0) g_mask_fmt = i32 ? 1 : (f32 ? 2 : 0);
}

// ---------------- CSR build (keyed by dst) ----------------
__global__ void k_count(const int* __restrict__ ei) {
    int e = blockIdx.x * blockDim.x + threadIdx.x;
    if (e < NE) atomicAdd(&g_deg[ei[NE + e]], 1);
}

__global__ void k_scan() {   // exclusive prefix over g_deg -> g_rowstart/g_cursor
    __shared__ int sm[1024];
    const int ITEMS = 20;    // 1024*20 = 20480 >= NN
    int t = threadIdx.x;
    int base = t * ITEMS;
    int loc[ITEMS];
    int run = 0;
#pragma unroll
    for (int j = 0; j < ITEMS; j++) {
        int i = base + j;
        int v = (i < NN) ? g_deg[i] : 0;
        loc[j] = run; run += v;
    }
    sm[t] = run;
    __syncthreads();
    for (int off = 1; off < 1024; off <<= 1) {
        int v = (t >= off) ? sm[t - off] : 0;
        __syncthreads();
        sm[t] += v;
        __syncthreads();
    }
    int excl = sm[t] - run;
#pragma unroll
    for (int j = 0; j < ITEMS; j++) {
        int i = base + j;
        if (i < NN) { int v = excl + loc[j]; g_rowstart[i] = v; g_cursor[i] = v; }
    }
    if (t == 1023) g_rowstart[NN] = sm[1023];
}

__global__ void k_fill(const int* __restrict__ ei) {
    int e = blockIdx.x * blockDim.x + threadIdx.x;
    if (e < NE) {
        int d = ei[NE + e];
        int pos = atomicAdd(&g_cursor[d], 1);
        g_csr[pos] = ei[e];
    }
}

// ---------------- init: H[n][r][c] = drop ? 0 : x[n][c] ----------------
__global__ void k_init(const float* __restrict__ x, const unsigned char* __restrict__ dm) {
    int i = blockIdx.x * blockDim.x + threadIdx.x;   // float4 index
    if (i >= NN * (RC / 4)) return;
    int n   = i / (RC / 4);
    int rem = i - n * (RC / 4);       // 0..159
    int r   = rem >> 4;               // 16 float4 per run
    int c4  = rem & 15;
    int mi  = r * NN + n;
    int fmt = g_mask_fmt;
    bool drop;
    if (fmt == 0)      drop = dm[mi] != 0;
    else if (fmt == 1) drop = ((const int*)dm)[mi] != 0;
    else               drop = ((const float*)dm)[mi] != 0.f;
    float4 v = make_float4(0.f, 0.f, 0.f, 0.f);
    if (!drop) v = ((const float4*)x)[n * 16 + c4];
    ((float4*)g_H)[i] = v;
}

// ---------------- aggregation: Z[n] = H[n] + sum_{src->n} H[src] ----------------
__global__ void k_agg() {
    int warp = (blockIdx.x * blockDim.x + threadIdx.x) >> 5;
    int lane = threadIdx.x & 31;
    if (warp >= NN) return;
    const float4* __restrict__ Hv = (const float4*)g_H;
    float4* __restrict__ Zv = (float4*)g_Z;
    int s = g_rowstart[warp], e = g_rowstart[warp + 1];
    int selfb = warp * 160 + lane;
    float4 acc[5];
#pragma unroll
    for (int k = 0; k < 5; k++) acc[k] = Hv[selfb + k * 32];
    for (int idx = s; idx < e; idx++) {
        int src = g_csr[idx];
        int b = src * 160 + lane;
#pragma unroll
        for (int k = 0; k < 5; k++) {
            float4 v = Hv[b + k * 32];
            acc[k].x += v.x; acc[k].y += v.y; acc[k].z += v.z; acc[k].w += v.w;
        }
    }
#pragma unroll
    for (int k = 0; k < 5; k++) Zv[selfb + k * 32] = acc[k];
}

// ---------------- GEMM v6: smem-staged X, quarter-split, NAMED f32x2 accs ------
// Block = 64 rows. Stage X[64x64] into smem (stride-65 padding, BN1+relu applied
// during staging for APPLY). 8 warps = 2 row-subtiles x 4 column-quarters.
// Each lane: one row, 16 output cols in 8 NAMED u64 accumulators (no arrays ->
// nothing the compiler can demote to local memory).
// APPLY=false: X = g_Z (raw), Y = g_T
// APPLY=true : X = g_T (BN1+relu in staging), Y = g_Z

#define DO_K4(ZV, KK) {                                                          \
    unsigned long long zz;                                                       \
    asm("mov.b64 %0,{%1,%1};" : "=l"(zz) : "f"(ZV));                             \
    const ulonglong2* wp = reinterpret_cast<const ulonglong2*>(&sW[(KK)][qb]);   \
    ulonglong2 wa = wp[0], wb = wp[1];                                           \
    asm("fma.rn.f32x2 %0,%1,%2,%0;" : "+l"(a0) : "l"(zz), "l"(wa.x));            \
    asm("fma.rn.f32x2 %0,%1,%2,%0;" : "+l"(a1) : "l"(zz), "l"(wa.y));            \
    asm("fma.rn.f32x2 %0,%1,%2,%0;" : "+l"(a2) : "l"(zz), "l"(wb.x));            \
    asm("fma.rn.f32x2 %0,%1,%2,%0;" : "+l"(a3) : "l"(zz), "l"(wb.y));            \
    ulonglong2 wc = wp[2], wd = wp[3];                                           \
    asm("fma.rn.f32x2 %0,%1,%2,%0;" : "+l"(a4) : "l"(zz), "l"(wc.x));            \
    asm("fma.rn.f32x2 %0,%1,%2,%0;" : "+l"(a5) : "l"(zz), "l"(wc.y));            \
    asm("fma.rn.f32x2 %0,%1,%2,%0;" : "+l"(a6) : "l"(zz), "l"(wd.x));            \
    asm("fma.rn.f32x2 %0,%1,%2,%0;" : "+l"(a7) : "l"(zz), "l"(wd.y)); }

template <bool APPLY>
__global__ void __launch_bounds__(256) k_gemm6(const float* __restrict__ Wg,
                                               const float* __restrict__ bg) {
    __shared__ unsigned long long sW[64][32];   // W as col-pairs [k][c2], 16KB
    __shared__ unsigned long long sbp[32];      // bias col-pairs
    __shared__ float sA[64], sC[64];
    __shared__ float sX[64 * 65];               // staged X, stride 65 (16.6KB)
    const float* __restrict__ X = APPLY ? g_T : g_Z;
    float*       __restrict__ Y = APPLY ? g_Z : g_T;
    int tid = threadIdx.x;
    for (int idx = tid; idx < 2048; idx += 256) {        // 64*32 pairs
        float2 w2 = ((const float2*)Wg)[idx];
        unsigned long long p;
        asm("mov.b64 %0,{%1,%2};" : "=l"(p) : "f"(w2.x), "f"(w2.y));
        sW[idx >> 5][idx & 31] = p;
    }
    if (tid < 32) {
        float b0 = bg[2 * tid], b1 = bg[2 * tid + 1];
        unsigned long long p;
        asm("mov.b64 %0,{%1,%2};" : "=l"(p) : "f"(b0), "f"(b1));
        sbp[tid] = p;
    }
    if (tid < 64) {
        if (APPLY) { sA[tid] = g_affA[tid]; sC[tid] = g_affC[tid]; }
        else       { sA[tid] = 1.f;        sC[tid] = 0.f; }
    }
    __syncthreads();

    int lane = tid & 31;
    int w    = tid >> 5;
    int qd   = w & 3;            // column quarter 0..3
    int rt   = w >> 2;           // row subtile 0..1
    int qb   = qd * 8;           // u64 offset into sW row
    int lrow = rt * 32 + lane;   // row within block tile

    for (int t = blockIdx.x; t < NBT; t += gridDim.x) {
        // ---- stage 64 rows of X (coalesced), apply BN1+relu if APPLY ----
        const float4* xs = ((const float4*)X) + t * 1024;
#pragma unroll
        for (int i = tid; i < 1024; i += 256) {
            float4 v = xs[i];
            int row = i >> 4, cb = (i & 15) * 4;
            if (APPLY) {
                v.x = fmaxf(fmaf(v.x, sA[cb],     sC[cb]),     0.f);
                v.y = fmaxf(fmaf(v.y, sA[cb + 1], sC[cb + 1]), 0.f);
                v.z = fmaxf(fmaf(v.z, sA[cb + 2], sC[cb + 2]), 0.f);
                v.w = fmaxf(fmaf(v.w, sA[cb + 3], sC[cb + 3]), 0.f);
            }
            float* d = &sX[row * 65 + cb];
            d[0] = v.x; d[1] = v.y; d[2] = v.z; d[3] = v.w;
        }
        __syncthreads();

        // ---- compute: this warp's (row subtile, column quarter) ----
        unsigned long long a0 = sbp[qb],     a1 = sbp[qb + 1],
                           a2 = sbp[qb + 2], a3 = sbp[qb + 3],
                           a4 = sbp[qb + 4], a5 = sbp[qb + 5],
                           a6 = sbp[qb + 6], a7 = sbp[qb + 7];
        const float* xr = &sX[lrow * 65];
#pragma unroll
        for (int k = 0; k < 64; k += 4) {
            float z0 = xr[k], z1 = xr[k + 1], z2 = xr[k + 2], z3 = xr[k + 3];
            DO_K4(z0, k);
            DO_K4(z1, k + 1);
            DO_K4(z2, k + 2);
            DO_K4(z3, k + 3);
        }
        int grow = t * 64 + lrow;
        ulonglong2* __restrict__ yp = (ulonglong2*)(Y + grow * 64 + qd * 16);
        ulonglong2 o0; o0.x = a0; o0.y = a1; yp[0] = o0;
        ulonglong2 o1; o1.x = a2; o1.y = a3; yp[1] = o1;
        ulonglong2 o2; o2.x = a4; o2.y = a5; yp[2] = o2;
        ulonglong2 o3; o3.x = a6; o3.y = a7; yp[3] = o3;
        __syncthreads();   // protect sX before next stage
    }
}

// ---------------- column stats (sum / sumsq) over [ROWS, 64] -------------------
template <bool SRCT>
__global__ void __launch_bounds__(256) k_colstats(int slot) {
    const float4* __restrict__ S = (const float4*)(SRCT ? g_T : g_Z);
    __shared__ float ss[64], sq[64];
    int tid = threadIdx.x;
    if (tid < 64) { ss[tid] = 0.f; sq[tid] = 0.f; }
    __syncthreads();
    int c4 = tid & 15;            // fixed float4-column per thread
    int rlane = tid >> 4;         // 0..15
    int rstride = gridDim.x * 16;
    float s0 = 0, s1 = 0, s2 = 0, s3 = 0, q0 = 0, q1 = 0, q2 = 0, q3 = 0;
    for (int r = blockIdx.x * 16 + rlane; r < ROWS; r += rstride) {
        float4 v = S[r * 16 + c4];
        s0 += v.x; q0 += v.x * v.x;
        s1 += v.y; q1 += v.y * v.y;
        s2 += v.z; q2 += v.z * v.z;
        s3 += v.w; q3 += v.w * v.w;
    }
    atomicAdd(&ss[c4 * 4 + 0], s0); atomicAdd(&sq[c4 * 4 + 0], q0);
    atomicAdd(&ss[c4 * 4 + 1], s1); atomicAdd(&sq[c4 * 4 + 1], q1);
    atomicAdd(&ss[c4 * 4 + 2], s2); atomicAdd(&sq[c4 * 4 + 2], q2);
    atomicAdd(&ss[c4 * 4 + 3], s3); atomicAdd(&sq[c4 * 4 + 3], q3);
    __syncthreads();
    if (tid < 64) {
        atomicAdd(&g_sum[slot][tid],   (double)ss[tid]);
        atomicAdd(&g_sumsq[slot][tid], (double)sq[tid]);
    }
}

// ---------------- BN stats -> per-column affine ----------------
__global__ void k_stats(const float* __restrict__ g, const float* __restrict__ b, int slot) {
    int t = threadIdx.x;
    double mu  = g_sum[slot][t]   / (double)ROWS;
    double var = g_sumsq[slot][t] / (double)ROWS - mu * mu;
    float A = g[t] * rsqrtf((float)var + BN_EPS);
    g_affA[t] = A;
    g_affC[t] = b[t] - (float)mu * A;
}

// ---------------- normalize (BN2+relu) -> H, plus per-level pooling ----------------
// NORM=false: src = g_H, no write (level 0 pooling only)
// NORM=true : src = g_Z (T2 raw), write H = relu(T2*A+C)
template <bool NORM>
__global__ void k_norm_pool(const int* __restrict__ batch, int lvl) {
    int warp = (blockIdx.x * blockDim.x + threadIdx.x) >> 5;
    int lane = threadIdx.x & 31;
    if (warp >= NN) return;
    const float2* __restrict__ S = (const float2*)(NORM ? g_Z : g_H);
    float2* __restrict__ Hd = (float2*)g_H;
    float A0 = 0.f, A1 = 0.f, C0 = 0.f, C1 = 0.f;
    if (NORM) {
        A0 = g_affA[2 * lane];     A1 = g_affA[2 * lane + 1];
        C0 = g_affC[2 * lane];     C1 = g_affC[2 * lane + 1];
    }
    float mx = 0.f, my = 0.f;
    int base = warp * 320 + lane;   // float2 units: row = 320 float2
#pragma unroll
    for (int r = 0; r < RR; r++) {
        float2 v = S[base + r * 32];
        if (NORM) {
            v.x = fmaxf(fmaf(v.x, A0, C0), 0.f);
            v.y = fmaxf(fmaf(v.y, A1, C1), 0.f);
            Hd[base + r * 32] = v;
        }
        mx += v.x; my += v.y;
    }
    int gidx = batch[warp];
    float* p = &g_pooled[lvl * (NG * CC) + gidx * CC + 2 * lane];
    atomicAdd(p,     mx * 0.1f);
    atomicAdd(p + 1, my * 0.1f);
}

// ---------------- final: sum_l pooled[l] @ fc_w[l] + fc_b[l], log_softmax ------
__global__ void k_final(const float* __restrict__ fcw, const float* __restrict__ fcb,
                        float* __restrict__ out) {
    int g = blockIdx.x;
    int lane = threadIdx.x;
    float acc = -1e30f;
    if (lane < NCLS) {
        acc = 0.f;
#pragma unroll
        for (int l = 0; l < NLAY + 1; l++) {
            acc += fcb[l * NCLS + lane];
            const float* p = &g_pooled[l * (NG * CC) + g * CC];
            const float* w = &fcw[l * (CC * NCLS) + lane];
            for (int c = 0; c < CC; c++) acc = fmaf(p[c], w[c * NCLS], acc);
        }
    }
    float mx = acc;
#pragma unroll
    for (int j = 0; j < NCLS; j++) mx = fmaxf(mx, __shfl_sync(0xffffffffu, acc, j));
    float se = 0.f;
#pragma unroll
    for (int j = 0; j < NCLS; j++) se += expf(__shfl_sync(0xffffffffu, acc, j) - mx);
    if (lane < NCLS) out[g * NCLS + lane] = acc - mx - logf(se);
}

// ---------------- launch ----------------
extern "C" void kernel_launch(void* const* d_in, const int* in_sizes, int n_in,
                              void* d_out, int out_size) {
    const float* x   = (const float*)d_in[0];
    const int*   ei  = (const int*)d_in[1];
    const int*   bat = (const int*)d_in[2];
    const unsigned char* dm = (const unsigned char*)d_in[3];
    const float* cw1 = (const float*)d_in[4];
    const float* cb1 = (const float*)d_in[5];
    const float* bg1 = (const float*)d_in[6];
    const float* bb1 = (const float*)d_in[7];
    const float* cw2 = (const float*)d_in[8];
    const float* cb2 = (const float*)d_in[9];
    const float* bng = (const float*)d_in[10];
    const float* bnb = (const float*)d_in[11];
    const float* fcw = (const float*)d_in[12];
    const float* fcb = (const float*)d_in[13];
    float* out = (float*)d_out;

    // CSR build (dst-keyed)
    k_zero_deg<<<(NN + 255) / 256, 256>>>();
    k_count<<<(NE + 255) / 256, 256>>>(ei);
    k_scan<<<1, 1024>>>();
    k_fill<<<(NE + 255) / 256, 256>>>(ei);

    // init H with node-drop
    k_detect<<<1, 32>>>(dm);
    k_init<<<(NN * (RC / 4) + 255) / 256, 256>>>(x, dm);

    k_zero_misc<<<((NLAY + 1) * NG * CC + 255) / 256, 256>>>();
    k_norm_pool<false><<<(NN * 32 + 255) / 256, 256>>>(bat, 0);   // level 0 pooling

    for (int i = 0; i < NLAY; i++) {
        k_agg<<<(NN * 32 + 255) / 256, 256>>>();
        k_gemm6<false><<<592, 256>>>(cw1 + i * 4096, cb1 + i * 64);
        k_colstats<true><<<296, 256>>>(2 * i);
        k_stats<<<1, 64>>>(bg1 + i * 64, bb1 + i * 64, 2 * i);
        k_gemm6<true><<<592, 256>>>(cw2 + i * 4096, cb2 + i * 64);
        k_colstats<false><<<296, 256>>>(2 * i + 1);
        k_stats<<<1, 64>>>(bng + i * 64, bnb + i * 64, 2 * i + 1);
        k_norm_pool<true><<<(NN * 32 + 255) / 256, 256>>>(bat, i + 1);
    }

    k_final<<<NG, 32>>>(fcw, fcb, out);
}